// round 6
// baseline (speedup 1.0000x reference)
#include <cuda_runtime.h>
#include <cuda_fp16.h>
#include <cstdint>

#define Bn 32
#define Cn 64
#define Hn 64
#define Wn 64
#define In 128
#define RT 2
#define WPAD 72
#define BROWS 288              // 4*72 input rows
#define BSTRIDE 272            // 64 half2 + 16B pad -> ldmatrix conflict-free
#define ASTRIDE 48             // 16 fp16 + 16B pad
#define ACHUNK (128 * ASTRIDE) // 6144
#define SLOT (2 * ACHUNK)      // 12288
#define NSTAGE 36              // 9 taps * 4 stages (2 k-chunks each)
#define SM_A 0
#define SM_B (2 * SLOT)        // 24576
#define SMEM_TOTAL (SM_B + BROWS * BSTRIDE)  // 102912

__device__ __align__(16) unsigned char g_A[NSTAGE * SLOT]; // flat stream of 72 chunks
__device__ float g_nt3[In];

// ---------------- prep ----------------
__global__ void prep_A(const float* __restrict__ tp, const float* __restrict__ sw) {
    int idx = blockIdx.x * 256 + threadIdx.x;
    if (idx >= 9 * 8 * 128 * 16) return;
    int e     = idx & 15;
    int row   = (idx >> 4) & 127;
    int chunk = (idx >> 11) & 7;
    int tap   = idx >> 14;
    int kk = chunk * 16 + e;
    int c = kk >> 1, s = kk & 1;
    int kh = tap / 3, kw = tap - kh * 3;
    int widx = ((row * Cn + c) * 3 + kh) * 3 + kw;
    float w = fabsf(sw[widx]);
    float t = tp[widx];
    float val = s ? -w : 2.0f * w * t;
    *(__half*)(g_A + ((size_t)tap * 8 + chunk) * ACHUNK + row * ASTRIDE + e * 2) =
        __float2half_rn(val);
}

__global__ void prep_t3(const float* __restrict__ tp, const float* __restrict__ sw) {
    int i = blockIdx.x;
    int c = threadIdx.x;
    float s = 0.f;
    int base = (i * Cn + c) * 9;
#pragma unroll
    for (int tap = 0; tap < 9; tap++) {
        float w = fabsf(sw[base + tap]);
        float t = tp[base + tap];
        s += w * t * t;
    }
    __shared__ float red[64];
    red[c] = s;
    __syncthreads();
    for (int off = 32; off > 0; off >>= 1) {
        if (c < off) red[c] += red[c + off];
        __syncthreads();
    }
    if (c == 0) g_nt3[i] = -red[0];
}

// ---------------- helpers ----------------
__device__ __forceinline__ uint32_t smem_u32(const void* p) {
    uint32_t a;
    asm("{ .reg .u64 t; cvta.to.shared.u64 t, %1; cvt.u32.u64 %0, t; }" : "=r"(a) : "l"(p));
    return a;
}
__device__ __forceinline__ void cp16(uint32_t dst, const void* src) {
    asm volatile("cp.async.cg.shared.global [%0], [%1], 16;" :: "r"(dst), "l"(src) : "memory");
}
__device__ __forceinline__ void cp_commit() {
    asm volatile("cp.async.commit_group;" ::: "memory");
}
__device__ __forceinline__ void ldmx4(uint32_t* r, uint32_t addr) {
    asm volatile("ldmatrix.sync.aligned.m8n8.x4.shared.b16 {%0,%1,%2,%3}, [%4];"
                 : "=r"(r[0]), "=r"(r[1]), "=r"(r[2]), "=r"(r[3]) : "r"(addr));
}
__device__ __forceinline__ void mma16816(float* c, const uint32_t* a,
                                         const uint32_t b0, const uint32_t b1) {
    asm volatile(
        "mma.sync.aligned.m16n8k16.row.col.f32.f16.f16.f32 "
        "{%0,%1,%2,%3}, {%4,%5,%6,%7}, {%8,%9}, {%0,%1,%2,%3};"
        : "+f"(c[0]), "+f"(c[1]), "+f"(c[2]), "+f"(c[3])
        : "r"(a[0]), "r"(a[1]), "r"(a[2]), "r"(a[3]), "r"(b0), "r"(b1));
}

// ---------------- main: grid (32 row-tiles, 32 batches), 256 threads, occ 2 ----------------
__global__ void __launch_bounds__(256, 2) sim_mma(const float* __restrict__ x,
                                                  float* __restrict__ out) {
    extern __shared__ __align__(16) unsigned char smem[];
    const uint32_t sb = smem_u32(smem);
    const int tid  = threadIdx.x;
    const int lane = tid & 31;
    const int warp = tid >> 5;
    const int wm = warp & 1;    // instances [wm*64, wm*64+64)
    const int wn = warp >> 1;   // 32 positions: row (wn>>1), cols (wn&1)*32..+32
    const int b  = blockIdx.y;
    const int y0 = blockIdx.x * RT;

    // prefetch stage 0
    for (int j = tid * 16; j < SLOT; j += 256 * 16) cp16(sb + SM_A + j, g_A + j);
    cp_commit();

    // ---- B fill, coalesced: one warp per (c, li) row, contiguous gx per lane ----
    const float* xb = x + (size_t)b * Cn * Hn * Wn;
    for (int rowid = warp; rowid < Cn * 4; rowid += 8) {
        int c  = rowid >> 2;
        int li = rowid & 3;
        int gy = y0 + li - 1;
        const bool yok = (unsigned)gy < Hn;
        const float* src = xb + (c * Hn + gy) * Wn;
        uint32_t dst = sb + SM_B + (uint32_t)(li * WPAD) * BSTRIDE + c * 4;
#pragma unroll
        for (int k2 = 0; k2 < 3; k2++) {
            int lx = lane + k2 * 32;
            if (lx < WPAD) {
                int gx = lx - 1;
                float v = (yok && (unsigned)gx < Wn) ? src[gx] : 0.f;
                __half2 h = __floats2half2_rn(v, v * v);
                *(uint32_t*)((unsigned char*)smem + SM_B + (li * WPAD + lx) * BSTRIDE + c * 4) =
                    *(uint32_t*)&h;
            }
        }
        (void)dst;
    }

    // ---- per-lane ldmatrix base addresses ----
    uint32_t arow[4];
#pragma unroll
    for (int t = 0; t < 4; t++)
        arow[t] = (uint32_t)((wm * 64 + t * 16 + (lane & 15)) * ASTRIDE) + ((lane >> 4) * 16);
    uint32_t bb[2];
#pragma unroll
    for (int j2 = 0; j2 < 2; j2++) {
        int xo = wn * 32 + j2 * 16 + ((lane >> 4) & 1) * 8 + (lane & 7);
        int r  = (xo >> 6) * WPAD + (xo & 63);
        bb[j2] = sb + SM_B + (uint32_t)(r * BSTRIDE) + ((lane >> 3) & 1) * 16;
    }

    float acc[4][4][4];
#pragma unroll
    for (int t = 0; t < 4; t++)
#pragma unroll
        for (int j = 0; j < 4; j++)
#pragma unroll
            for (int q = 0; q < 4; q++) acc[t][j][q] = 0.f;

    // ---- main loop: 36 stages of 2 k-chunks, 2-slot ring ----
    for (int s = 0; s < NSTAGE; s++) {
        if (s < NSTAGE - 1) {
            uint32_t d = sb + SM_A + ((s + 1) & 1) * SLOT;
            const unsigned char* g = g_A + (size_t)(s + 1) * SLOT;
            for (int j = tid * 16; j < SLOT; j += 256 * 16) cp16(d + j, g + j);
            cp_commit();
            asm volatile("cp.async.wait_group 1;" ::: "memory");
        } else {
            asm volatile("cp.async.wait_group 0;" ::: "memory");
        }
        __syncthreads();

        const int tap = s >> 2;
        const int kh = tap / 3, kw = tap - kh * 3;
        const uint32_t tapoff = (uint32_t)((kh * WPAD + kw) * BSTRIDE);
        const uint32_t abase = sb + SM_A + (s & 1) * SLOT;

#pragma unroll
        for (int c2 = 0; c2 < 2; c2++) {
            const int chunk = (s & 3) * 2 + c2;
            uint32_t a[4][4];
#pragma unroll
            for (int t = 0; t < 4; t++)
                ldmx4(a[t], abase + c2 * ACHUNK + arow[t]);
            uint32_t br[2][4];
#pragma unroll
            for (int j2 = 0; j2 < 2; j2++)
                ldmx4(br[j2], bb[j2] + tapoff + chunk * 32);
#pragma unroll
            for (int t = 0; t < 4; t++)
#pragma unroll
                for (int j2 = 0; j2 < 2; j2++) {
                    mma16816(acc[t][2 * j2],     a[t], br[j2][0], br[j2][1]);
                    mma16816(acc[t][2 * j2 + 1], a[t], br[j2][2], br[j2][3]);
                }
        }
        __syncthreads();
    }

    // ---- epilogue ----
    const int gy = y0 + (wn >> 1);
#pragma unroll
    for (int t = 0; t < 4; t++) {
        const int m_lo = wm * 64 + t * 16 + (lane >> 2);
        const int m_hi = m_lo + 8;
        const float bias_lo = g_nt3[m_lo];
        const float bias_hi = g_nt3[m_hi];
        float* o_lo = out + (((size_t)b * In + m_lo) * Hn + gy) * Wn;
        float* o_hi = out + (((size_t)b * In + m_hi) * Hn + gy) * Wn;
#pragma unroll
        for (int j = 0; j < 4; j++) {
            const int xc = (wn & 1) * 32 + j * 8 + 2 * (lane & 3);
            *(float2*)(o_lo + xc) = make_float2(acc[t][j][0] + bias_lo, acc[t][j][1] + bias_lo);
            *(float2*)(o_hi + xc) = make_float2(acc[t][j][2] + bias_hi, acc[t][j][3] + bias_hi);
        }
    }
}

extern "C" void kernel_launch(void* const* d_in, const int* in_sizes, int n_in,
                              void* d_out, int out_size) {
    const float* x  = (const float*)d_in[0];
    const float* tp = (const float*)d_in[1];
    const float* sw = (const float*)d_in[2];
    float* out = (float*)d_out;

    cudaFuncSetAttribute(sim_mma, cudaFuncAttributeMaxDynamicSharedMemorySize, SMEM_TOTAL);

    prep_A<<<(9 * 8 * 128 * 16 + 255) / 256, 256>>>(tp, sw);
    prep_t3<<<In, 64>>>(tp, sw);
    sim_mma<<<dim3(32, Bn), 256, SMEM_TOTAL>>>(x, out);
}

// round 7
// speedup vs baseline: 1.0123x; 1.0123x over previous
#include <cuda_runtime.h>
#include <cuda_fp16.h>
#include <cstdint>

#define Bn 32
#define Cn 64
#define Hn 64
#define Wn 64
#define In 128
#define RT 2
#define WPAD 72
#define BROWS 288              // 4*72 input rows
#define BSTRIDE 272            // 64 half2 + 16B pad -> ldmatrix conflict-free
#define ASTRIDE 48             // 16 fp16 + 16B pad
#define ACHUNK (128 * ASTRIDE) // 6144
#define SLOT (2 * ACHUNK)      // 12288
#define NSTAGE 36              // 9 taps * 4 stages (2 k-chunks each)
#define SM_A 0
#define SM_B (2 * SLOT)        // 24576
#define SMEM_TOTAL (SM_B + BROWS * BSTRIDE)  // 102912

__device__ __align__(16) unsigned char g_A[NSTAGE * SLOT]; // flat stream of 72 chunks
__device__ float g_nt3[In];

// ---------------- prep ----------------
__global__ void prep_A(const float* __restrict__ tp, const float* __restrict__ sw) {
    int idx = blockIdx.x * 256 + threadIdx.x;
    if (idx >= 9 * 8 * 128 * 16) return;
    int e     = idx & 15;
    int row   = (idx >> 4) & 127;
    int chunk = (idx >> 11) & 7;
    int tap   = idx >> 14;
    int kk = chunk * 16 + e;
    int c = kk >> 1, s = kk & 1;
    int kh = tap / 3, kw = tap - kh * 3;
    int widx = ((row * Cn + c) * 3 + kh) * 3 + kw;
    float w = fabsf(sw[widx]);
    float t = tp[widx];
    float val = s ? -w : 2.0f * w * t;
    *(__half*)(g_A + ((size_t)tap * 8 + chunk) * ACHUNK + row * ASTRIDE + e * 2) =
        __float2half_rn(val);
}

__global__ void prep_t3(const float* __restrict__ tp, const float* __restrict__ sw) {
    int i = blockIdx.x;
    int c = threadIdx.x;
    float s = 0.f;
    int base = (i * Cn + c) * 9;
#pragma unroll
    for (int tap = 0; tap < 9; tap++) {
        float w = fabsf(sw[base + tap]);
        float t = tp[base + tap];
        s += w * t * t;
    }
    __shared__ float red[64];
    red[c] = s;
    __syncthreads();
    for (int off = 32; off > 0; off >>= 1) {
        if (c < off) red[c] += red[c + off];
        __syncthreads();
    }
    if (c == 0) g_nt3[i] = -red[0];
}

// ---------------- helpers ----------------
__device__ __forceinline__ uint32_t smem_u32(const void* p) {
    uint32_t a;
    asm("{ .reg .u64 t; cvta.to.shared.u64 t, %1; cvt.u32.u64 %0, t; }" : "=r"(a) : "l"(p));
    return a;
}
__device__ __forceinline__ void cp16(uint32_t dst, const void* src) {
    asm volatile("cp.async.cg.shared.global [%0], [%1], 16;" :: "r"(dst), "l"(src) : "memory");
}
__device__ __forceinline__ void cp_commit() {
    asm volatile("cp.async.commit_group;" ::: "memory");
}
__device__ __forceinline__ void ldmx4(uint32_t* r, uint32_t addr) {
    asm volatile("ldmatrix.sync.aligned.m8n8.x4.shared.b16 {%0,%1,%2,%3}, [%4];"
                 : "=r"(r[0]), "=r"(r[1]), "=r"(r[2]), "=r"(r[3]) : "r"(addr));
}
__device__ __forceinline__ void mma16816(float* c, const uint32_t* a,
                                         const uint32_t b0, const uint32_t b1) {
    asm volatile(
        "mma.sync.aligned.m16n8k16.row.col.f32.f16.f16.f32 "
        "{%0,%1,%2,%3}, {%4,%5,%6,%7}, {%8,%9}, {%0,%1,%2,%3};"
        : "+f"(c[0]), "+f"(c[1]), "+f"(c[2]), "+f"(c[3])
        : "r"(a[0]), "r"(a[1]), "r"(a[2]), "r"(a[3]), "r"(b0), "r"(b1));
}

// ---------------- main: grid (32 row-tiles, 32 batches), 256 threads, occ 2 ----------------
__global__ void __launch_bounds__(256, 2) sim_mma(const float* __restrict__ x,
                                                  float* __restrict__ out) {
    extern __shared__ __align__(16) unsigned char smem[];
    const uint32_t sb = smem_u32(smem);
    const int tid  = threadIdx.x;
    const int lane = tid & 31;
    const int warp = tid >> 5;
    const int wm = warp & 1;    // instances [wm*64, wm*64+64)
    const int wn = warp >> 1;   // 32 positions: row (wn>>1), cols (wn&1)*32..+32
    const int b  = blockIdx.y;
    const int y0 = blockIdx.x * RT;

    // prefetch stage 0
    for (int j = tid * 16; j < SLOT; j += 256 * 16) cp16(sb + SM_A + j, g_A + j);
    cp_commit();

    // ---- B fill, coalesced: one warp per (c, li) row, contiguous gx per lane ----
    const float* xb = x + (size_t)b * Cn * Hn * Wn;
    for (int rowid = warp; rowid < Cn * 4; rowid += 8) {
        int c  = rowid >> 2;
        int li = rowid & 3;
        int gy = y0 + li - 1;
        const bool yok = (unsigned)gy < Hn;
        const float* src = xb + (c * Hn + gy) * Wn;
        uint32_t dst = sb + SM_B + (uint32_t)(li * WPAD) * BSTRIDE + c * 4;
#pragma unroll
        for (int k2 = 0; k2 < 3; k2++) {
            int lx = lane + k2 * 32;
            if (lx < WPAD) {
                int gx = lx - 1;
                float v = (yok && (unsigned)gx < Wn) ? src[gx] : 0.f;
                __half2 h = __floats2half2_rn(v, v * v);
                *(uint32_t*)((unsigned char*)smem + SM_B + (li * WPAD + lx) * BSTRIDE + c * 4) =
                    *(uint32_t*)&h;
            }
        }
        (void)dst;
    }

    // ---- per-lane ldmatrix base addresses ----
    uint32_t arow[4];
#pragma unroll
    for (int t = 0; t < 4; t++)
        arow[t] = (uint32_t)((wm * 64 + t * 16 + (lane & 15)) * ASTRIDE) + ((lane >> 4) * 16);
    uint32_t bb[2];
#pragma unroll
    for (int j2 = 0; j2 < 2; j2++) {
        int xo = wn * 32 + j2 * 16 + ((lane >> 4) & 1) * 8 + (lane & 7);
        int r  = (xo >> 6) * WPAD + (xo & 63);
        bb[j2] = sb + SM_B + (uint32_t)(r * BSTRIDE) + ((lane >> 3) & 1) * 16;
    }

    float acc[4][4][4];
#pragma unroll
    for (int t = 0; t < 4; t++)
#pragma unroll
        for (int j = 0; j < 4; j++)
#pragma unroll
            for (int q = 0; q < 4; q++) acc[t][j][q] = 0.f;

    // ---- main loop: 36 stages of 2 k-chunks, 2-slot ring ----
    for (int s = 0; s < NSTAGE; s++) {
        if (s < NSTAGE - 1) {
            uint32_t d = sb + SM_A + ((s + 1) & 1) * SLOT;
            const unsigned char* g = g_A + (size_t)(s + 1) * SLOT;
            for (int j = tid * 16; j < SLOT; j += 256 * 16) cp16(d + j, g + j);
            cp_commit();
            asm volatile("cp.async.wait_group 1;" ::: "memory");
        } else {
            asm volatile("cp.async.wait_group 0;" ::: "memory");
        }
        __syncthreads();

        const int tap = s >> 2;
        const int kh = tap / 3, kw = tap - kh * 3;
        const uint32_t tapoff = (uint32_t)((kh * WPAD + kw) * BSTRIDE);
        const uint32_t abase = sb + SM_A + (s & 1) * SLOT;

#pragma unroll
        for (int c2 = 0; c2 < 2; c2++) {
            const int chunk = (s & 3) * 2 + c2;
            uint32_t a[4][4];
#pragma unroll
            for (int t = 0; t < 4; t++)
                ldmx4(a[t], abase + c2 * ACHUNK + arow[t]);
            uint32_t br[2][4];
#pragma unroll
            for (int j2 = 0; j2 < 2; j2++)
                ldmx4(br[j2], bb[j2] + tapoff + chunk * 32);
#pragma unroll
            for (int t = 0; t < 4; t++)
#pragma unroll
                for (int j2 = 0; j2 < 2; j2++) {
                    mma16816(acc[t][2 * j2],     a[t], br[j2][0], br[j2][1]);
                    mma16816(acc[t][2 * j2 + 1], a[t], br[j2][2], br[j2][3]);
                }
        }
        __syncthreads();
    }

    // ---- epilogue ----
    const int gy = y0 + (wn >> 1);
#pragma unroll
    for (int t = 0; t < 4; t++) {
        const int m_lo = wm * 64 + t * 16 + (lane >> 2);
        const int m_hi = m_lo + 8;
        const float bias_lo = g_nt3[m_lo];
        const float bias_hi = g_nt3[m_hi];
        float* o_lo = out + (((size_t)b * In + m_lo) * Hn + gy) * Wn;
        float* o_hi = out + (((size_t)b * In + m_hi) * Hn + gy) * Wn;
#pragma unroll
        for (int j = 0; j < 4; j++) {
            const int xc = (wn & 1) * 32 + j * 8 + 2 * (lane & 3);
            *(float2*)(o_lo + xc) = make_float2(acc[t][j][0] + bias_lo, acc[t][j][1] + bias_lo);
            *(float2*)(o_hi + xc) = make_float2(acc[t][j][2] + bias_hi, acc[t][j][3] + bias_hi);
        }
    }
}

extern "C" void kernel_launch(void* const* d_in, const int* in_sizes, int n_in,
                              void* d_out, int out_size) {
    const float* x  = (const float*)d_in[0];
    const float* tp = (const float*)d_in[1];
    const float* sw = (const float*)d_in[2];
    float* out = (float*)d_out;

    cudaFuncSetAttribute(sim_mma, cudaFuncAttributeMaxDynamicSharedMemorySize, SMEM_TOTAL);

    prep_A<<<(9 * 8 * 128 * 16 + 255) / 256, 256>>>(tp, sw);
    prep_t3<<<In, 64>>>(tp, sw);
    sim_mma<<<dim3(32, Bn), 256, SMEM_TOTAL>>>(x, out);
}